// round 12
// baseline (speedup 1.0000x reference)
#include <cuda_runtime.h>
#include <cuda_bf16.h>
#include <cstdint>

#define NB 8
#define CD 256
#define LD 6400
#define NHEADS 8
#define HC 32

// Scratch (device globals -- no allocation allowed)
__device__ float g_Q[NB * CD * LD];
__device__ float g_K[NB * CD * LD];     // holds exp(K) after projection
__device__ float g_V[NB * CD * LD];
__device__ float g_CTX[NB * NHEADS * HC * HC];
__device__ float g_ksum[NB * CD];
__device__ __nv_bfloat16 g_Qbf[NB * CD * LD];
__device__ __nv_bfloat16 g_Kbf[NB * CD * LD];
__device__ __nv_bfloat16 g_Vbf[NB * CD * LD];
__device__ __nv_bfloat16 g_ATTbf[NB * CD * LD];
__device__ __nv_bfloat16 g_Wt[4 * 256 * 256];   // k-major bf16: Wq,Wk,Wv,Wr

// ---------------------------------------------------------------------------
// mma.sync / ldmatrix / cp.async helpers (baseline PTX, works on compute_103)
// ---------------------------------------------------------------------------
__device__ __forceinline__ uint32_t smem_u32(const void* p) {
    uint32_t a;
    asm("{ .reg .u64 t; cvta.to.shared.u64 t, %1; cvt.u32.u64 %0, t; }"
        : "=r"(a) : "l"(p));
    return a;
}

__device__ __forceinline__ void ldsm4t(uint32_t* r, uint32_t addr) {
    asm volatile("ldmatrix.sync.aligned.m8n8.x4.trans.shared.b16 {%0,%1,%2,%3}, [%4];"
                 : "=r"(r[0]), "=r"(r[1]), "=r"(r[2]), "=r"(r[3]) : "r"(addr));
}

__device__ __forceinline__ void mma16816(float* c, uint32_t a0, uint32_t a1,
                                         uint32_t a2, uint32_t a3,
                                         uint32_t b0, uint32_t b1) {
    asm volatile(
        "mma.sync.aligned.m16n8k16.row.col.f32.bf16.bf16.f32 "
        "{%0,%1,%2,%3}, {%4,%5,%6,%7}, {%8,%9}, {%0,%1,%2,%3};"
        : "+f"(c[0]), "+f"(c[1]), "+f"(c[2]), "+f"(c[3])
        : "r"(a0), "r"(a1), "r"(a2), "r"(a3), "r"(b0), "r"(b1));
}

__device__ __forceinline__ void cpasync16(uint32_t saddr, const void* g) {
    asm volatile("cp.async.cg.shared.global [%0], [%1], 16;"
                 :: "r"(saddr), "l"(g) : "memory");
}
__device__ __forceinline__ void cpasync_commit() {
    asm volatile("cp.async.commit_group;" ::: "memory");
}
__device__ __forceinline__ void cpasync_wait0() {
    asm volatile("cp.async.wait_group 0;" ::: "memory");
}
__device__ __forceinline__ void cpasync_wait1() {
    asm volatile("cp.async.wait_group 1;" ::: "memory");
}

// ---------------------------------------------------------------------------
// Fused conversion: q/k/v fp32 -> bf16 (MLP=4 batched) + 4x W transpose.
// ---------------------------------------------------------------------------
#define CVT_STRIDE 819200   // (NB*CD*LD/4) / 4 float4s per j-slice

__global__ __launch_bounds__(256) void cvt_all_kernel(
    const float* __restrict__ qf, const float* __restrict__ kf,
    const float* __restrict__ vf,
    const float* __restrict__ Wq, const float* __restrict__ Wk,
    const float* __restrict__ Wv, const float* __restrict__ Wr)
{
    const int y = blockIdx.y;
    if (y < 3) {
        const float* src = (y == 0) ? kf : (y == 1) ? qf : vf;
        __nv_bfloat16* dst = (y == 0) ? g_Kbf : (y == 1) ? g_Qbf : g_Vbf;
        const float4* s4 = (const float4*)src;
        const size_t base = (size_t)blockIdx.x * 256 + threadIdx.x;
        float4 v[4];
#pragma unroll
        for (int j = 0; j < 4; ++j) v[j] = s4[base + (size_t)j * CVT_STRIDE];
#pragma unroll
        for (int j = 0; j < 4; ++j) {
            union { __nv_bfloat162 h[2]; unsigned long long u; } u;
            u.h[0] = __float22bfloat162_rn(make_float2(v[j].x, v[j].y));
            u.h[1] = __float22bfloat162_rn(make_float2(v[j].z, v[j].w));
            *(unsigned long long*)&dst[(base + (size_t)j * CVT_STRIDE) * 4] = u.u;
        }
    } else {
        if (blockIdx.x >= 64) return;
        int t = blockIdx.x * 256 + threadIdx.x;   // 0..16383
        const float* Ws[4] = {Wq, Wk, Wv, Wr};
#pragma unroll
        for (int w = 0; w < 4; ++w) {
            const float* W = Ws[w];
            __nv_bfloat16* D = g_Wt + w * 65536;
            for (int idx = t; idx < 65536; idx += 16384) {
                int m = idx >> 8, k = idx & 255;
                D[k * 256 + m] = __float2bfloat16(W[idx]);   // W[m*256+k]
            }
        }
    }
}

// ---------------------------------------------------------------------------
// Zero g_CTX and g_ksum.
// ---------------------------------------------------------------------------
__global__ void zero_kernel()
{
    int i = blockIdx.x * 256 + threadIdx.x;
    if (i < NB * NHEADS * HC * HC) g_CTX[i] = 0.0f;
    int j = i - NB * NHEADS * HC * HC;
    if (j >= 0 && j < NB * CD) g_ksum[j] = 0.0f;
}

// ---------------------------------------------------------------------------
// HMMA GEMM: Y[n, m, l] = f(sum_k Wt[k,m] * Xbf[n,k,l] + bias[m] (+ resid))
// where f = exp if bit proj of expmask is set (for the K projection).
// Block tile 128(m) x 128(l), BK=32, 8 warps, 3-stage cp.async pipeline.
// ---------------------------------------------------------------------------
#define SB 136                     // bf16 row stride (272B, conflict-free ldsm)
#define REG_EL (32 * SB)           // 4352 bf16 per operand region
#define STAGE_BYTES (2 * REG_EL * 2)   // A + B regions = 17408 bytes
#define GEMM_SMEM (3 * STAGE_BYTES)    // 52224 bytes

__global__ __launch_bounds__(256, 2) void hmma_gemm_kernel(
    const __nv_bfloat16* __restrict__ X0, const __nv_bfloat16* __restrict__ X1,
    const __nv_bfloat16* __restrict__ X2,
    const __nv_bfloat16* __restrict__ Wt0, const __nv_bfloat16* __restrict__ Wt1,
    const __nv_bfloat16* __restrict__ Wt2,
    const float* __restrict__ b0p, const float* __restrict__ b1p,
    const float* __restrict__ b2p,
    float* __restrict__ Y0, float* __restrict__ Y1, float* __restrict__ Y2,
    const float* __restrict__ resid, int expmask)
{
    extern __shared__ __align__(16) __nv_bfloat16 dsm[];

    const int tid  = threadIdx.x;
    const int wid  = tid >> 5;
    const int lane = tid & 31;
    const int l0   = blockIdx.x * 128;
    const int m0   = blockIdx.y * 128;
    const int proj = blockIdx.z >> 3;
    const int nb   = blockIdx.z & 7;

    const __nv_bfloat16* X;
    const __nv_bfloat16* Wt;
    const float* bias;
    float* Y;
    if (proj == 0)      { X = X0; Wt = Wt0; bias = b0p; Y = Y0; }
    else if (proj == 1) { X = X1; Wt = Wt1; bias = b1p; Y = Y1; }
    else                { X = X2; Wt = Wt2; bias = b2p; Y = Y2; }
    const bool do_exp = (expmask >> proj) & 1;

    const int m0w = (wid & 3) * 32;   // warp m offset in block
    const int n0w = (wid >> 2) * 64;  // warp n offset in block

    const __nv_bfloat16* Xn = X + (size_t)nb * CD * LD;
    float* Yn = Y + (size_t)nb * CD * LD;
    const float* Rn = resid ? resid + (size_t)nb * CD * LD : nullptr;

    float acc[2][8][4];
#pragma unroll
    for (int i = 0; i < 2; i++)
#pragma unroll
        for (int j = 0; j < 8; j++)
#pragma unroll
            for (int e = 0; e < 4; e++) acc[i][j][e] = 0.0f;

    const uint32_t smBase = smem_u32(dsm);
    const uint32_t chunk = (uint32_t)((tid >> 4) * (SB * 2) + (tid & 15) * 16);
    const uint32_t aOff = (uint32_t)((lane & 15) * (SB * 2) +
                                     (m0w + ((lane >> 4) << 3)) * 2);
    const uint32_t bOff = (uint32_t)((lane & 15) * (SB * 2) +
                                     (n0w + ((lane >> 4) << 3)) * 2);
    const int g_k  = tid >> 4;    // 0..15
    const int g_c8 = (tid & 15) * 8;

#define ISSUE(c)                                                               \
    {                                                                          \
        uint32_t sb = smBase + ((c) % 3) * STAGE_BYTES;                        \
        const __nv_bfloat16* gA = Wt + ((c) * 32 + g_k) * 256 + m0 + g_c8;     \
        cpasync16(sb + chunk, gA);                                             \
        cpasync16(sb + chunk + 16 * SB * 2, gA + 16 * 256);                    \
        const __nv_bfloat16* gB =                                              \
            Xn + (size_t)((c) * 32 + g_k) * LD + l0 + g_c8;                    \
        cpasync16(sb + 2 * REG_EL + chunk, gB);                                \
        cpasync16(sb + 2 * REG_EL + chunk + 16 * SB * 2, gB + (size_t)16 * LD);\
        cpasync_commit();                                                      \
    }

    ISSUE(0);
    ISSUE(1);

#pragma unroll
    for (int c = 0; c < 8; ++c) {
        if (c < 7) cpasync_wait1(); else cpasync_wait0();
        __syncthreads();
        if (c < 6) ISSUE(c + 2);

        uint32_t aA = smBase + (c % 3) * STAGE_BYTES + aOff;
        uint32_t bA = aA - aOff + 2 * REG_EL + bOff;
#pragma unroll
        for (int ks = 0; ks < 2; ++ks) {
            uint32_t a4[2][4];
#pragma unroll
            for (int im = 0; im < 2; ++im)
                ldsm4t(a4[im], aA + (uint32_t)(ks * 16 * SB * 2 + im * 32));
#pragma unroll
            for (int jp = 0; jp < 4; ++jp) {
                uint32_t b4[4];
                ldsm4t(b4, bA + (uint32_t)(ks * 16 * SB * 2 + jp * 32));
#pragma unroll
                for (int im = 0; im < 2; ++im) {
                    // A fragment from transposed ldsm: {r0, r2, r1, r3}
                    mma16816(acc[im][jp * 2 + 0], a4[im][0], a4[im][2],
                             a4[im][1], a4[im][3], b4[0], b4[1]);
                    mma16816(acc[im][jp * 2 + 1], a4[im][0], a4[im][2],
                             a4[im][1], a4[im][3], b4[2], b4[3]);
                }
            }
        }
    }

    // ---- epilogue: regs -> global, + bias (+ residual) (+ exp)
    const int qr = lane >> 2;        // 0..7
    const int qc = (lane & 3) * 2;   // 0,2,4,6
#pragma unroll
    for (int im = 0; im < 2; ++im) {
        int mA = m0 + m0w + im * 16 + qr;
        int mB = mA + 8;
        float bA = bias[mA];
        float bB = bias[mB];
#pragma unroll
        for (int jn = 0; jn < 8; ++jn) {
            int n = l0 + n0w + jn * 8 + qc;
            size_t gA = (size_t)mA * LD + n;
            size_t gB = (size_t)mB * LD + n;
            float o0 = acc[im][jn][0] + bA;
            float o1 = acc[im][jn][1] + bA;
            float o2 = acc[im][jn][2] + bB;
            float o3 = acc[im][jn][3] + bB;
            if (Rn) {
                float2 rA = *(const float2*)(Rn + gA);
                float2 rB = *(const float2*)(Rn + gB);
                o0 += rA.x; o1 += rA.y; o2 += rB.x; o3 += rB.y;
            }
            if (do_exp) {
                o0 = __expf(o0); o1 = __expf(o1);
                o2 = __expf(o2); o3 = __expf(o3);
            }
            float2 vA = {o0, o1};
            float2 vB = {o2, o3};
            *(float2*)(Yn + gA) = vA;
            *(float2*)(Yn + gB) = vB;
        }
    }
}

// ---------------------------------------------------------------------------
// context[n,h,kc,vc] = sum_l expK[n,h,kc,l] * V[n,h,vc,l]   (unnormalized)
// expK precomputed by the K-projection GEMM epilogue. Register-tiled 4x4.
// Also accumulates g_ksum via the vc-group-0 threads.
// ---------------------------------------------------------------------------
#define CPAD 36   // floats per l-row (16B aligned, conflict-free fp4 reads)

__global__ __launch_bounds__(256) void context_kernel()
{
    __shared__ float skT[128][CPAD];
    __shared__ float svT[128][CPAD];
    const int n = blockIdx.z, h = blockIdx.y;
    const size_t base = (((size_t)n * NHEADS + h) * HC) * LD;
    const int rowbase = n * CD + h * HC;
    const int tid = threadIdx.x;
    const int grp = tid >> 6;        // 0..3 (l sub-range within 128-tile)
    const int t64 = tid & 63;
    const int kc0 = (t64 >> 3) * 4;  // 0,4,..,28
    const int vc0 = (t64 & 7) * 4;   // 0,4,..,28
    const bool do_ksum = ((t64 & 7) == 0);

    float acc[4][4];
#pragma unroll
    for (int i = 0; i < 4; ++i)
#pragma unroll
        for (int j = 0; j < 4; ++j) acc[i][j] = 0.0f;
    float ks[4] = {0.f, 0.f, 0.f, 0.f};

    for (int t = 0; t < 5; ++t) {
        const int l0 = blockIdx.x * 640 + t * 128;
#pragma unroll
        for (int s = 0; s < 16; s++) {
            int idx = tid + s * 256;
            int c = idx >> 7, l = idx & 127;
            skT[l][c] = g_K[base + (size_t)c * LD + l0 + l];   // already exp'd
            svT[l][c] = g_V[base + (size_t)c * LD + l0 + l];
        }
        __syncthreads();
#pragma unroll 4
        for (int li = 0; li < 32; ++li) {
            int l = grp * 32 + li;
            float4 a4 = *(const float4*)&skT[l][kc0];
            float4 b4 = *(const float4*)&svT[l][vc0];
            float a[4] = {a4.x, a4.y, a4.z, a4.w};
            float b[4] = {b4.x, b4.y, b4.z, b4.w};
#pragma unroll
            for (int i = 0; i < 4; ++i)
#pragma unroll
                for (int j = 0; j < 4; ++j)
                    acc[i][j] += a[i] * b[j];
            if (do_ksum) {
                ks[0] += a[0]; ks[1] += a[1]; ks[2] += a[2]; ks[3] += a[3];
            }
        }
        __syncthreads();
    }

    if (do_ksum) {
#pragma unroll
        for (int i = 0; i < 4; ++i)
            atomicAdd(&g_ksum[rowbase + kc0 + i], ks[i]);
    }
    float* C = g_CTX + (((size_t)n * NHEADS + h) * HC) * HC;
#pragma unroll
    for (int i = 0; i < 4; ++i)
#pragma unroll
        for (int j = 0; j < 4; ++j)
            atomicAdd(&C[(kc0 + i) * HC + vc0 + j], acc[i][j]);
}

// ---------------------------------------------------------------------------
// attended[n,h,vc,l] = sum_kc (ctx[n,h,kc,vc]/ksum[kc]) * softmax_C(q)[n,h,kc,l]
// Writes bf16 directly for the recovery GEMM.
// ---------------------------------------------------------------------------
__global__ __launch_bounds__(128) void attend_kernel()
{
    __shared__ float4 sctx[32][8];
    const int n = blockIdx.z, h = blockIdx.y;
    const int tid = threadIdx.x;
    const int rowbase = n * CD + h * HC;
    {
        const float4* C = (const float4*)(g_CTX + (((size_t)n * NHEADS + h) * HC) * HC);
#pragma unroll
        for (int s = 0; s < 2; s++) {
            int idx = tid + s * 128;
            float inv = 1.0f / g_ksum[rowbase + (idx >> 3)];
            float4 v = C[idx];
            v.x *= inv; v.y *= inv; v.z *= inv; v.w *= inv;
            sctx[idx >> 3][idx & 7] = v;
        }
    }
    __syncthreads();

    const int l = blockIdx.x * 128 + tid;
    const size_t base = (((size_t)n * NHEADS + h) * HC) * LD + l;

    float q[HC];
    float mx = -1e30f;
#pragma unroll
    for (int c = 0; c < HC; c++) {
        q[c] = g_Q[base + (size_t)c * LD];
        mx = fmaxf(mx, q[c]);
    }
    float s = 0.0f;
#pragma unroll
    for (int c = 0; c < HC; c++) {
        q[c] = __expf(q[c] - mx);
        s += q[c];
    }
    float inv = 1.0f / s;
#pragma unroll
    for (int c = 0; c < HC; c++) q[c] *= inv;

    float acc[HC];
#pragma unroll
    for (int v = 0; v < HC; v++) acc[v] = 0.0f;

#pragma unroll
    for (int kc = 0; kc < HC; kc++) {
        float a = q[kc];
#pragma unroll
        for (int vq = 0; vq < 8; vq++) {
            float4 c4 = sctx[kc][vq];
            acc[vq * 4 + 0] += a * c4.x;
            acc[vq * 4 + 1] += a * c4.y;
            acc[vq * 4 + 2] += a * c4.z;
            acc[vq * 4 + 3] += a * c4.w;
        }
    }
#pragma unroll
    for (int v = 0; v < HC; v++)
        g_ATTbf[base + (size_t)v * LD] = __float2bfloat16(acc[v]);
}

// ---------------------------------------------------------------------------
extern "C" void kernel_launch(void* const* d_in, const int* in_sizes, int n_in,
                              void* d_out, int out_size)
{
    const float* qf = (const float*)d_in[0];
    const float* kf = (const float*)d_in[1];
    const float* vf = (const float*)d_in[2];
    const float* Wq = (const float*)d_in[3];
    const float* bq = (const float*)d_in[4];
    const float* Wk = (const float*)d_in[5];
    const float* bk = (const float*)d_in[6];
    const float* Wv = (const float*)d_in[7];
    const float* bv = (const float*)d_in[8];
    const float* Wr = (const float*)d_in[9];
    const float* br = (const float*)d_in[10];
    float* out = (float*)d_out;

    float *Q, *K, *V;
    __nv_bfloat16 *Qbf, *Kbf, *Vbf, *ATTbf, *Wt;
    cudaGetSymbolAddress((void**)&Q,     g_Q);
    cudaGetSymbolAddress((void**)&K,     g_K);
    cudaGetSymbolAddress((void**)&V,     g_V);
    cudaGetSymbolAddress((void**)&Qbf,   g_Qbf);
    cudaGetSymbolAddress((void**)&Kbf,   g_Kbf);
    cudaGetSymbolAddress((void**)&Vbf,   g_Vbf);
    cudaGetSymbolAddress((void**)&ATTbf, g_ATTbf);
    cudaGetSymbolAddress((void**)&Wt,    g_Wt);
    __nv_bfloat16* Wtq = Wt;
    __nv_bfloat16* Wtk = Wt + 65536;
    __nv_bfloat16* Wtv = Wt + 2 * 65536;
    __nv_bfloat16* Wtr = Wt + 3 * 65536;

    cudaFuncSetAttribute(hmma_gemm_kernel,
                         cudaFuncAttributeMaxDynamicSharedMemorySize, GEMM_SMEM);

    cvt_all_kernel<<<dim3(3200, 4), 256>>>(qf, kf, vf, Wq, Wk, Wv, Wr);    // 1
    zero_kernel<<<264, 256>>>();                                           // 2

    // fused Q/K/V projections: proj = blockIdx.z >> 3; exp on proj 0 (K)
    dim3 fused_grid(LD / 128, CD / 128, 3 * NB);
    hmma_gemm_kernel<<<fused_grid, 256, GEMM_SMEM>>>(                      // 3
        Kbf, Qbf, Vbf, Wtk, Wtq, Wtv, bk, bq, bv, K, Q, V, nullptr, 1);

    context_kernel<<<dim3(10, NHEADS, NB), 256>>>();                       // 4 (ncu)
    attend_kernel<<<dim3(LD / 128, NHEADS, NB), 128>>>();                  // 5

    dim3 gemm_grid(LD / 128, CD / 128, NB);
    hmma_gemm_kernel<<<gemm_grid, 256, GEMM_SMEM>>>(                       // 6
        ATTbf, ATTbf, ATTbf, Wtr, Wtr, Wtr, br, br, br, out, out, out, qf, 0);
}

// round 13
// speedup vs baseline: 1.0842x; 1.0842x over previous
#include <cuda_runtime.h>
#include <cuda_bf16.h>
#include <cstdint>

#define NB 8
#define CD 256
#define LD 6400
#define NHEADS 8
#define HC 32

// Scratch (device globals -- no allocation allowed)
__device__ float g_Q[NB * CD * LD];
__device__ float g_K[NB * CD * LD];
__device__ float g_V[NB * CD * LD];
__device__ float g_CTX[NB * NHEADS * HC * HC];
__device__ float g_ksum[NB * CD];
__device__ __nv_bfloat16 g_Qbf[NB * CD * LD];
__device__ __nv_bfloat16 g_Kbf[NB * CD * LD];
__device__ __nv_bfloat16 g_Vbf[NB * CD * LD];
__device__ __nv_bfloat16 g_ATTbf[NB * CD * LD];
__device__ __nv_bfloat16 g_Wt[4 * 256 * 256];   // k-major bf16: Wq,Wk,Wv,Wr

// ---------------------------------------------------------------------------
// mma.sync / ldmatrix / cp.async helpers (baseline PTX, works on compute_103)
// ---------------------------------------------------------------------------
__device__ __forceinline__ uint32_t smem_u32(const void* p) {
    uint32_t a;
    asm("{ .reg .u64 t; cvta.to.shared.u64 t, %1; cvt.u32.u64 %0, t; }"
        : "=r"(a) : "l"(p));
    return a;
}

__device__ __forceinline__ void ldsm4t(uint32_t* r, uint32_t addr) {
    asm volatile("ldmatrix.sync.aligned.m8n8.x4.trans.shared.b16 {%0,%1,%2,%3}, [%4];"
                 : "=r"(r[0]), "=r"(r[1]), "=r"(r[2]), "=r"(r[3]) : "r"(addr));
}

__device__ __forceinline__ void mma16816(float* c, uint32_t a0, uint32_t a1,
                                         uint32_t a2, uint32_t a3,
                                         uint32_t b0, uint32_t b1) {
    asm volatile(
        "mma.sync.aligned.m16n8k16.row.col.f32.bf16.bf16.f32 "
        "{%0,%1,%2,%3}, {%4,%5,%6,%7}, {%8,%9}, {%0,%1,%2,%3};"
        : "+f"(c[0]), "+f"(c[1]), "+f"(c[2]), "+f"(c[3])
        : "r"(a0), "r"(a1), "r"(a2), "r"(a3), "r"(b0), "r"(b1));
}

__device__ __forceinline__ void cpasync16(uint32_t saddr, const void* g) {
    asm volatile("cp.async.cg.shared.global [%0], [%1], 16;"
                 :: "r"(saddr), "l"(g) : "memory");
}
__device__ __forceinline__ void cpasync_commit() {
    asm volatile("cp.async.commit_group;" ::: "memory");
}
__device__ __forceinline__ void cpasync_wait0() {
    asm volatile("cp.async.wait_group 0;" ::: "memory");
}
__device__ __forceinline__ void cpasync_wait1() {
    asm volatile("cp.async.wait_group 1;" ::: "memory");
}

// ---------------------------------------------------------------------------
// Fused conversion: q/k/v fp32 -> bf16 (MLP=4 batched) + 4x W transpose.
// ---------------------------------------------------------------------------
#define CVT_STRIDE 819200   // (NB*CD*LD/4) / 4 float4s per j-slice

__global__ __launch_bounds__(256) void cvt_all_kernel(
    const float* __restrict__ qf, const float* __restrict__ kf,
    const float* __restrict__ vf,
    const float* __restrict__ Wq, const float* __restrict__ Wk,
    const float* __restrict__ Wv, const float* __restrict__ Wr)
{
    const int y = blockIdx.y;
    if (y < 3) {
        const float* src = (y == 0) ? kf : (y == 1) ? qf : vf;
        __nv_bfloat16* dst = (y == 0) ? g_Kbf : (y == 1) ? g_Qbf : g_Vbf;
        const float4* s4 = (const float4*)src;
        const size_t base = (size_t)blockIdx.x * 256 + threadIdx.x;
        float4 v[4];
#pragma unroll
        for (int j = 0; j < 4; ++j) v[j] = s4[base + (size_t)j * CVT_STRIDE];
#pragma unroll
        for (int j = 0; j < 4; ++j) {
            union { __nv_bfloat162 h[2]; unsigned long long u; } u;
            u.h[0] = __float22bfloat162_rn(make_float2(v[j].x, v[j].y));
            u.h[1] = __float22bfloat162_rn(make_float2(v[j].z, v[j].w));
            *(unsigned long long*)&dst[(base + (size_t)j * CVT_STRIDE) * 4] = u.u;
        }
    } else {
        if (blockIdx.x >= 64) return;
        int t = blockIdx.x * 256 + threadIdx.x;   // 0..16383
        const float* Ws[4] = {Wq, Wk, Wv, Wr};
#pragma unroll
        for (int w = 0; w < 4; ++w) {
            const float* W = Ws[w];
            __nv_bfloat16* D = g_Wt + w * 65536;
            for (int idx = t; idx < 65536; idx += 16384) {
                int m = idx >> 8, k = idx & 255;
                D[k * 256 + m] = __float2bfloat16(W[idx]);   // W[m*256+k]
            }
        }
    }
}

// ---------------------------------------------------------------------------
// Zero g_CTX and g_ksum.
// ---------------------------------------------------------------------------
__global__ void zero_kernel()
{
    int i = blockIdx.x * 256 + threadIdx.x;
    if (i < NB * NHEADS * HC * HC) g_CTX[i] = 0.0f;
    int j = i - NB * NHEADS * HC * HC;
    if (j >= 0 && j < NB * CD) g_ksum[j] = 0.0f;
}

// ---------------------------------------------------------------------------
// HMMA GEMM: Y[n, m, l] = sum_k Wt[k,m] * Xbf[n,k,l] + bias[m] (+ resid)
// Block tile 128(m) x 128(l), BK=32, 8 warps, 3-stage cp.async pipeline.
// ---------------------------------------------------------------------------
#define SB 136                     // bf16 row stride (272B, conflict-free ldsm)
#define REG_EL (32 * SB)           // 4352 bf16 per operand region
#define STAGE_BYTES (2 * REG_EL * 2)   // A + B regions = 17408 bytes
#define GEMM_SMEM (3 * STAGE_BYTES)    // 52224 bytes

__global__ __launch_bounds__(256, 2) void hmma_gemm_kernel(
    const __nv_bfloat16* __restrict__ X0, const __nv_bfloat16* __restrict__ X1,
    const __nv_bfloat16* __restrict__ X2,
    const __nv_bfloat16* __restrict__ Wt0, const __nv_bfloat16* __restrict__ Wt1,
    const __nv_bfloat16* __restrict__ Wt2,
    const float* __restrict__ b0p, const float* __restrict__ b1p,
    const float* __restrict__ b2p,
    float* __restrict__ Y0, float* __restrict__ Y1, float* __restrict__ Y2,
    const float* __restrict__ resid)
{
    extern __shared__ __align__(16) __nv_bfloat16 dsm[];

    const int tid  = threadIdx.x;
    const int wid  = tid >> 5;
    const int lane = tid & 31;
    const int l0   = blockIdx.x * 128;
    const int m0   = blockIdx.y * 128;
    const int proj = blockIdx.z >> 3;
    const int nb   = blockIdx.z & 7;

    const __nv_bfloat16* X;
    const __nv_bfloat16* Wt;
    const float* bias;
    float* Y;
    if (proj == 0)      { X = X0; Wt = Wt0; bias = b0p; Y = Y0; }
    else if (proj == 1) { X = X1; Wt = Wt1; bias = b1p; Y = Y1; }
    else                { X = X2; Wt = Wt2; bias = b2p; Y = Y2; }

    const int m0w = (wid & 3) * 32;   // warp m offset in block
    const int n0w = (wid >> 2) * 64;  // warp n offset in block

    const __nv_bfloat16* Xn = X + (size_t)nb * CD * LD;
    float* Yn = Y + (size_t)nb * CD * LD;
    const float* Rn = resid ? resid + (size_t)nb * CD * LD : nullptr;

    float acc[2][8][4];
#pragma unroll
    for (int i = 0; i < 2; i++)
#pragma unroll
        for (int j = 0; j < 8; j++)
#pragma unroll
            for (int e = 0; e < 4; e++) acc[i][j][e] = 0.0f;

    const uint32_t smBase = smem_u32(dsm);
    const uint32_t chunk = (uint32_t)((tid >> 4) * (SB * 2) + (tid & 15) * 16);
    const uint32_t aOff = (uint32_t)((lane & 15) * (SB * 2) +
                                     (m0w + ((lane >> 4) << 3)) * 2);
    const uint32_t bOff = (uint32_t)((lane & 15) * (SB * 2) +
                                     (n0w + ((lane >> 4) << 3)) * 2);
    const int g_k  = tid >> 4;    // 0..15
    const int g_c8 = (tid & 15) * 8;

#define ISSUE(c)                                                               \
    {                                                                          \
        uint32_t sb = smBase + ((c) % 3) * STAGE_BYTES;                        \
        const __nv_bfloat16* gA = Wt + ((c) * 32 + g_k) * 256 + m0 + g_c8;     \
        cpasync16(sb + chunk, gA);                                             \
        cpasync16(sb + chunk + 16 * SB * 2, gA + 16 * 256);                    \
        const __nv_bfloat16* gB =                                              \
            Xn + (size_t)((c) * 32 + g_k) * LD + l0 + g_c8;                    \
        cpasync16(sb + 2 * REG_EL + chunk, gB);                                \
        cpasync16(sb + 2 * REG_EL + chunk + 16 * SB * 2, gB + (size_t)16 * LD);\
        cpasync_commit();                                                      \
    }

    ISSUE(0);
    ISSUE(1);

#pragma unroll
    for (int c = 0; c < 8; ++c) {
        if (c < 7) cpasync_wait1(); else cpasync_wait0();
        __syncthreads();
        if (c < 6) ISSUE(c + 2);

        uint32_t aA = smBase + (c % 3) * STAGE_BYTES + aOff;
        uint32_t bA = aA - aOff + 2 * REG_EL + bOff;
#pragma unroll
        for (int ks = 0; ks < 2; ++ks) {
            uint32_t a4[2][4];
#pragma unroll
            for (int im = 0; im < 2; ++im)
                ldsm4t(a4[im], aA + (uint32_t)(ks * 16 * SB * 2 + im * 32));
#pragma unroll
            for (int jp = 0; jp < 4; ++jp) {
                uint32_t b4[4];
                ldsm4t(b4, bA + (uint32_t)(ks * 16 * SB * 2 + jp * 32));
#pragma unroll
                for (int im = 0; im < 2; ++im) {
                    // A fragment from transposed ldsm: {r0, r2, r1, r3}
                    mma16816(acc[im][jp * 2 + 0], a4[im][0], a4[im][2],
                             a4[im][1], a4[im][3], b4[0], b4[1]);
                    mma16816(acc[im][jp * 2 + 1], a4[im][0], a4[im][2],
                             a4[im][1], a4[im][3], b4[2], b4[3]);
                }
            }
        }
    }

    // ---- epilogue: regs -> global, + bias (+ residual)
    const int qr = lane >> 2;        // 0..7
    const int qc = (lane & 3) * 2;   // 0,2,4,6
#pragma unroll
    for (int im = 0; im < 2; ++im) {
        int mA = m0 + m0w + im * 16 + qr;
        int mB = mA + 8;
        float bA = bias[mA];
        float bB = bias[mB];
#pragma unroll
        for (int jn = 0; jn < 8; ++jn) {
            int n = l0 + n0w + jn * 8 + qc;
            size_t gA = (size_t)mA * LD + n;
            size_t gB = (size_t)mB * LD + n;
            float o0 = acc[im][jn][0] + bA;
            float o1 = acc[im][jn][1] + bA;
            float o2 = acc[im][jn][2] + bB;
            float o3 = acc[im][jn][3] + bB;
            if (Rn) {
                float2 rA = *(const float2*)(Rn + gA);
                float2 rB = *(const float2*)(Rn + gB);
                o0 += rA.x; o1 += rA.y; o2 += rB.x; o3 += rB.y;
            }
            float2 vA = {o0, o1};
            float2 vB = {o2, o3};
            *(float2*)(Yn + gA) = vA;
            *(float2*)(Yn + gB) = vB;
        }
    }
}

// ---------------------------------------------------------------------------
// context[n,h,kc,vc] = sum_l exp(K[n,h,kc,l]) * V[n,h,vc,l]   (unnormalized)
// Register-tiled 4x4 + register-prefetch software pipeline: tile t+1's LDGs
// are issued before tile t's compute so DRAM latency hides behind FMA work.
// Also accumulates g_ksum via the vc-group-0 threads.
// ---------------------------------------------------------------------------
#define CPAD 36   // floats per l-row (16B aligned, conflict-free fp4 reads)

__global__ __launch_bounds__(256) void context_kernel()
{
    __shared__ float skT[128][CPAD];
    __shared__ float svT[128][CPAD];
    const int n = blockIdx.z, h = blockIdx.y;
    const size_t base = (((size_t)n * NHEADS + h) * HC) * LD;
    const int rowbase = n * CD + h * HC;
    const int tid = threadIdx.x;
    const int grp = tid >> 6;        // 0..3 (l sub-range within 128-tile)
    const int t64 = tid & 63;
    const int kc0 = (t64 >> 3) * 4;  // 0,4,..,28
    const int vc0 = (t64 & 7) * 4;   // 0,4,..,28
    const bool do_ksum = ((t64 & 7) == 0);

    // per-thread staging element coords (16 per array)
    const int st_c = tid >> 7;       // contributes to c via idx = tid + s*256
    (void)st_c;

    float acc[4][4];
#pragma unroll
    for (int i = 0; i < 4; ++i)
#pragma unroll
        for (int j = 0; j < 4; ++j) acc[i][j] = 0.0f;
    float ks[4] = {0.f, 0.f, 0.f, 0.f};

    float rk[16], rv[16];

#define CTX_LOAD(t)                                                            \
    {                                                                          \
        const int l0c = blockIdx.x * 640 + (t) * 128;                          \
        _Pragma("unroll")                                                      \
        for (int s = 0; s < 16; s++) {                                         \
            int idx = tid + s * 256;                                           \
            int c = idx >> 7, l = idx & 127;                                   \
            rk[s] = g_K[base + (size_t)c * LD + l0c + l];                      \
            rv[s] = g_V[base + (size_t)c * LD + l0c + l];                      \
        }                                                                      \
    }

#define CTX_STORE()                                                            \
    {                                                                          \
        _Pragma("unroll")                                                      \
        for (int s = 0; s < 16; s++) {                                         \
            int idx = tid + s * 256;                                           \
            int c = idx >> 7, l = idx & 127;                                   \
            skT[l][c] = __expf(rk[s]);                                         \
            svT[l][c] = rv[s];                                                 \
        }                                                                      \
    }

    CTX_LOAD(0);

    for (int t = 0; t < 5; ++t) {
        CTX_STORE();
        __syncthreads();
        if (t < 4) CTX_LOAD(t + 1);   // LDGs in flight during compute

#pragma unroll 4
        for (int li = 0; li < 32; ++li) {
            int l = grp * 32 + li;
            float4 a4 = *(const float4*)&skT[l][kc0];
            float4 b4 = *(const float4*)&svT[l][vc0];
            float a[4] = {a4.x, a4.y, a4.z, a4.w};
            float b[4] = {b4.x, b4.y, b4.z, b4.w};
#pragma unroll
            for (int i = 0; i < 4; ++i)
#pragma unroll
                for (int j = 0; j < 4; ++j)
                    acc[i][j] += a[i] * b[j];
            if (do_ksum) {
                ks[0] += a[0]; ks[1] += a[1]; ks[2] += a[2]; ks[3] += a[3];
            }
        }
        __syncthreads();
    }

    if (do_ksum) {
#pragma unroll
        for (int i = 0; i < 4; ++i)
            atomicAdd(&g_ksum[rowbase + kc0 + i], ks[i]);
    }
    float* C = g_CTX + (((size_t)n * NHEADS + h) * HC) * HC;
#pragma unroll
    for (int i = 0; i < 4; ++i)
#pragma unroll
        for (int j = 0; j < 4; ++j)
            atomicAdd(&C[(kc0 + i) * HC + vc0 + j], acc[i][j]);
}

// ---------------------------------------------------------------------------
// attended[n,h,vc,l] = sum_kc (ctx[n,h,kc,vc]/ksum[kc]) * softmax_C(q)[n,h,kc,l]
// Writes bf16 directly for the recovery GEMM.
// ---------------------------------------------------------------------------
__global__ __launch_bounds__(128) void attend_kernel()
{
    __shared__ float4 sctx[32][8];
    const int n = blockIdx.z, h = blockIdx.y;
    const int tid = threadIdx.x;
    const int rowbase = n * CD + h * HC;
    {
        const float4* C = (const float4*)(g_CTX + (((size_t)n * NHEADS + h) * HC) * HC);
#pragma unroll
        for (int s = 0; s < 2; s++) {
            int idx = tid + s * 128;
            float inv = 1.0f / g_ksum[rowbase + (idx >> 3)];
            float4 v = C[idx];
            v.x *= inv; v.y *= inv; v.z *= inv; v.w *= inv;
            sctx[idx >> 3][idx & 7] = v;
        }
    }
    __syncthreads();

    const int l = blockIdx.x * 128 + tid;
    const size_t base = (((size_t)n * NHEADS + h) * HC) * LD + l;

    float q[HC];
    float mx = -1e30f;
#pragma unroll
    for (int c = 0; c < HC; c++) {
        q[c] = g_Q[base + (size_t)c * LD];
        mx = fmaxf(mx, q[c]);
    }
    float s = 0.0f;
#pragma unroll
    for (int c = 0; c < HC; c++) {
        q[c] = __expf(q[c] - mx);
        s += q[c];
    }
    float inv = 1.0f / s;
#pragma unroll
    for (int c = 0; c < HC; c++) q[c] *= inv;

    float acc[HC];
#pragma unroll
    for (int v = 0; v < HC; v++) acc[v] = 0.0f;

#pragma unroll
    for (int kc = 0; kc < HC; kc++) {
        float a = q[kc];
#pragma unroll
        for (int vq = 0; vq < 8; vq++) {
            float4 c4 = sctx[kc][vq];
            acc[vq * 4 + 0] += a * c4.x;
            acc[vq * 4 + 1] += a * c4.y;
            acc[vq * 4 + 2] += a * c4.z;
            acc[vq * 4 + 3] += a * c4.w;
        }
    }
#pragma unroll
    for (int v = 0; v < HC; v++)
        g_ATTbf[base + (size_t)v * LD] = __float2bfloat16(acc[v]);
}

// ---------------------------------------------------------------------------
extern "C" void kernel_launch(void* const* d_in, const int* in_sizes, int n_in,
                              void* d_out, int out_size)
{
    const float* qf = (const float*)d_in[0];
    const float* kf = (const float*)d_in[1];
    const float* vf = (const float*)d_in[2];
    const float* Wq = (const float*)d_in[3];
    const float* bq = (const float*)d_in[4];
    const float* Wk = (const float*)d_in[5];
    const float* bk = (const float*)d_in[6];
    const float* Wv = (const float*)d_in[7];
    const float* bv = (const float*)d_in[8];
    const float* Wr = (const float*)d_in[9];
    const float* br = (const float*)d_in[10];
    float* out = (float*)d_out;

    float *Q, *K, *V;
    __nv_bfloat16 *Qbf, *Kbf, *Vbf, *ATTbf, *Wt;
    cudaGetSymbolAddress((void**)&Q,     g_Q);
    cudaGetSymbolAddress((void**)&K,     g_K);
    cudaGetSymbolAddress((void**)&V,     g_V);
    cudaGetSymbolAddress((void**)&Qbf,   g_Qbf);
    cudaGetSymbolAddress((void**)&Kbf,   g_Kbf);
    cudaGetSymbolAddress((void**)&Vbf,   g_Vbf);
    cudaGetSymbolAddress((void**)&ATTbf, g_ATTbf);
    cudaGetSymbolAddress((void**)&Wt,    g_Wt);
    __nv_bfloat16* Wtq = Wt;
    __nv_bfloat16* Wtk = Wt + 65536;
    __nv_bfloat16* Wtv = Wt + 2 * 65536;
    __nv_bfloat16* Wtr = Wt + 3 * 65536;

    cudaFuncSetAttribute(hmma_gemm_kernel,
                         cudaFuncAttributeMaxDynamicSharedMemorySize, GEMM_SMEM);

    cvt_all_kernel<<<dim3(3200, 4), 256>>>(qf, kf, vf, Wq, Wk, Wv, Wr);    // 1
    zero_kernel<<<264, 256>>>();                                           // 2

    // fused Q/K/V projections: proj = blockIdx.z >> 3
    dim3 fused_grid(LD / 128, CD / 128, 3 * NB);
    hmma_gemm_kernel<<<fused_grid, 256, GEMM_SMEM>>>(                      // 3
        Kbf, Qbf, Vbf, Wtk, Wtq, Wtv, bk, bq, bv, K, Q, V, nullptr);

    context_kernel<<<dim3(10, NHEADS, NB), 256>>>();                       // 4 (ncu)
    attend_kernel<<<dim3(LD / 128, NHEADS, NB), 128>>>();                  // 5

    dim3 gemm_grid(LD / 128, CD / 128, NB);
    hmma_gemm_kernel<<<gemm_grid, 256, GEMM_SMEM>>>(                       // 6
        ATTbf, ATTbf, ATTbf, Wtr, Wtr, Wtr, br, br, br, out, out, out, qf);
}

// round 14
// speedup vs baseline: 1.1208x; 1.0337x over previous
#include <cuda_runtime.h>
#include <cuda_bf16.h>
#include <cstdint>

#define NB 8
#define CD 256
#define LD 6400
#define NHEADS 8
#define HC 32

// Scratch (device globals -- no allocation allowed)
__device__ float g_Q[NB * CD * LD];
__device__ float g_K[NB * CD * LD];
__device__ float g_V[NB * CD * LD];
__device__ float g_CTX[NB * NHEADS * HC * HC];
__device__ float g_ksum[NB * CD];
__device__ __nv_bfloat16 g_Qbf[NB * CD * LD];
__device__ __nv_bfloat16 g_Kbf[NB * CD * LD];
__device__ __nv_bfloat16 g_Vbf[NB * CD * LD];
__device__ __nv_bfloat16 g_ATTbf[NB * CD * LD];
__device__ __nv_bfloat16 g_Wt[4 * 256 * 256];   // k-major bf16: Wq,Wk,Wv,Wr

// ---------------------------------------------------------------------------
// mma.sync / ldmatrix / cp.async helpers (baseline PTX, works on compute_103)
// ---------------------------------------------------------------------------
__device__ __forceinline__ uint32_t smem_u32(const void* p) {
    uint32_t a;
    asm("{ .reg .u64 t; cvta.to.shared.u64 t, %1; cvt.u32.u64 %0, t; }"
        : "=r"(a) : "l"(p));
    return a;
}

__device__ __forceinline__ void ldsm4t(uint32_t* r, uint32_t addr) {
    asm volatile("ldmatrix.sync.aligned.m8n8.x4.trans.shared.b16 {%0,%1,%2,%3}, [%4];"
                 : "=r"(r[0]), "=r"(r[1]), "=r"(r[2]), "=r"(r[3]) : "r"(addr));
}

__device__ __forceinline__ void mma16816(float* c, uint32_t a0, uint32_t a1,
                                         uint32_t a2, uint32_t a3,
                                         uint32_t b0, uint32_t b1) {
    asm volatile(
        "mma.sync.aligned.m16n8k16.row.col.f32.bf16.bf16.f32 "
        "{%0,%1,%2,%3}, {%4,%5,%6,%7}, {%8,%9}, {%0,%1,%2,%3};"
        : "+f"(c[0]), "+f"(c[1]), "+f"(c[2]), "+f"(c[3])
        : "r"(a0), "r"(a1), "r"(a2), "r"(a3), "r"(b0), "r"(b1));
}

__device__ __forceinline__ void cpasync16(uint32_t saddr, const void* g) {
    asm volatile("cp.async.cg.shared.global [%0], [%1], 16;"
                 :: "r"(saddr), "l"(g) : "memory");
}
__device__ __forceinline__ void cpasync_commit() {
    asm volatile("cp.async.commit_group;" ::: "memory");
}
__device__ __forceinline__ void cpasync_wait0() {
    asm volatile("cp.async.wait_group 0;" ::: "memory");
}
__device__ __forceinline__ void cpasync_wait1() {
    asm volatile("cp.async.wait_group 1;" ::: "memory");
}

// ---------------------------------------------------------------------------
// Fused conversion: q/k/v fp32 -> bf16 (MLP=4 batched) + 4x W transpose.
// ---------------------------------------------------------------------------
#define CVT_STRIDE 819200   // (NB*CD*LD/4) / 4 float4s per j-slice

__global__ __launch_bounds__(256) void cvt_all_kernel(
    const float* __restrict__ qf, const float* __restrict__ kf,
    const float* __restrict__ vf,
    const float* __restrict__ Wq, const float* __restrict__ Wk,
    const float* __restrict__ Wv, const float* __restrict__ Wr)
{
    const int y = blockIdx.y;
    if (y < 3) {
        const float* src = (y == 0) ? kf : (y == 1) ? qf : vf;
        __nv_bfloat16* dst = (y == 0) ? g_Kbf : (y == 1) ? g_Qbf : g_Vbf;
        const float4* s4 = (const float4*)src;
        const size_t base = (size_t)blockIdx.x * 256 + threadIdx.x;
        float4 v[4];
#pragma unroll
        for (int j = 0; j < 4; ++j) v[j] = s4[base + (size_t)j * CVT_STRIDE];
#pragma unroll
        for (int j = 0; j < 4; ++j) {
            union { __nv_bfloat162 h[2]; unsigned long long u; } u;
            u.h[0] = __float22bfloat162_rn(make_float2(v[j].x, v[j].y));
            u.h[1] = __float22bfloat162_rn(make_float2(v[j].z, v[j].w));
            *(unsigned long long*)&dst[(base + (size_t)j * CVT_STRIDE) * 4] = u.u;
        }
    } else {
        if (blockIdx.x >= 64) return;
        int t = blockIdx.x * 256 + threadIdx.x;   // 0..16383
        const float* Ws[4] = {Wq, Wk, Wv, Wr};
#pragma unroll
        for (int w = 0; w < 4; ++w) {
            const float* W = Ws[w];
            __nv_bfloat16* D = g_Wt + w * 65536;
            for (int idx = t; idx < 65536; idx += 16384) {
                int m = idx >> 8, k = idx & 255;
                D[k * 256 + m] = __float2bfloat16(W[idx]);   // W[m*256+k]
            }
        }
    }
}

// ---------------------------------------------------------------------------
// Zero g_CTX and g_ksum.
// ---------------------------------------------------------------------------
__global__ void zero_kernel()
{
    int i = blockIdx.x * 256 + threadIdx.x;
    if (i < NB * NHEADS * HC * HC) g_CTX[i] = 0.0f;
    int j = i - NB * NHEADS * HC * HC;
    if (j >= 0 && j < NB * CD) g_ksum[j] = 0.0f;
}

// ---------------------------------------------------------------------------
// HMMA GEMM: Y[n, m, l] = sum_k Wt[k,m] * Xbf[n,k,l] + bias[m] (+ resid)
// Block tile 128(m) x 128(l), BK=32, 8 warps, 3-stage cp.async pipeline.
// ---------------------------------------------------------------------------
#define SB 136                     // bf16 row stride (272B, conflict-free ldsm)
#define REG_EL (32 * SB)           // 4352 bf16 per operand region
#define STAGE_BYTES (2 * REG_EL * 2)   // A + B regions = 17408 bytes
#define GEMM_SMEM (3 * STAGE_BYTES)    // 52224 bytes

__global__ __launch_bounds__(256, 2) void hmma_gemm_kernel(
    const __nv_bfloat16* __restrict__ X0, const __nv_bfloat16* __restrict__ X1,
    const __nv_bfloat16* __restrict__ X2,
    const __nv_bfloat16* __restrict__ Wt0, const __nv_bfloat16* __restrict__ Wt1,
    const __nv_bfloat16* __restrict__ Wt2,
    const float* __restrict__ b0p, const float* __restrict__ b1p,
    const float* __restrict__ b2p,
    float* __restrict__ Y0, float* __restrict__ Y1, float* __restrict__ Y2,
    const float* __restrict__ resid)
{
    extern __shared__ __align__(16) __nv_bfloat16 dsm[];

    const int tid  = threadIdx.x;
    const int wid  = tid >> 5;
    const int lane = tid & 31;
    const int l0   = blockIdx.x * 128;
    const int m0   = blockIdx.y * 128;
    const int proj = blockIdx.z >> 3;
    const int nb   = blockIdx.z & 7;

    const __nv_bfloat16* X;
    const __nv_bfloat16* Wt;
    const float* bias;
    float* Y;
    if (proj == 0)      { X = X0; Wt = Wt0; bias = b0p; Y = Y0; }
    else if (proj == 1) { X = X1; Wt = Wt1; bias = b1p; Y = Y1; }
    else                { X = X2; Wt = Wt2; bias = b2p; Y = Y2; }

    const int m0w = (wid & 3) * 32;   // warp m offset in block
    const int n0w = (wid >> 2) * 64;  // warp n offset in block

    const __nv_bfloat16* Xn = X + (size_t)nb * CD * LD;
    float* Yn = Y + (size_t)nb * CD * LD;
    const float* Rn = resid ? resid + (size_t)nb * CD * LD : nullptr;

    float acc[2][8][4];
#pragma unroll
    for (int i = 0; i < 2; i++)
#pragma unroll
        for (int j = 0; j < 8; j++)
#pragma unroll
            for (int e = 0; e < 4; e++) acc[i][j][e] = 0.0f;

    const uint32_t smBase = smem_u32(dsm);
    const uint32_t chunk = (uint32_t)((tid >> 4) * (SB * 2) + (tid & 15) * 16);
    const uint32_t aOff = (uint32_t)((lane & 15) * (SB * 2) +
                                     (m0w + ((lane >> 4) << 3)) * 2);
    const uint32_t bOff = (uint32_t)((lane & 15) * (SB * 2) +
                                     (n0w + ((lane >> 4) << 3)) * 2);
    const int g_k  = tid >> 4;    // 0..15
    const int g_c8 = (tid & 15) * 8;

#define ISSUE(c)                                                               \
    {                                                                          \
        uint32_t sb = smBase + ((c) % 3) * STAGE_BYTES;                        \
        const __nv_bfloat16* gA = Wt + ((c) * 32 + g_k) * 256 + m0 + g_c8;     \
        cpasync16(sb + chunk, gA);                                             \
        cpasync16(sb + chunk + 16 * SB * 2, gA + 16 * 256);                    \
        const __nv_bfloat16* gB =                                              \
            Xn + (size_t)((c) * 32 + g_k) * LD + l0 + g_c8;                    \
        cpasync16(sb + 2 * REG_EL + chunk, gB);                                \
        cpasync16(sb + 2 * REG_EL + chunk + 16 * SB * 2, gB + (size_t)16 * LD);\
        cpasync_commit();                                                      \
    }

    ISSUE(0);
    ISSUE(1);

#pragma unroll
    for (int c = 0; c < 8; ++c) {
        if (c < 7) cpasync_wait1(); else cpasync_wait0();
        __syncthreads();
        if (c < 6) ISSUE(c + 2);

        uint32_t aA = smBase + (c % 3) * STAGE_BYTES + aOff;
        uint32_t bA = aA - aOff + 2 * REG_EL + bOff;
#pragma unroll
        for (int ks = 0; ks < 2; ++ks) {
            uint32_t a4[2][4];
#pragma unroll
            for (int im = 0; im < 2; ++im)
                ldsm4t(a4[im], aA + (uint32_t)(ks * 16 * SB * 2 + im * 32));
#pragma unroll
            for (int jp = 0; jp < 4; ++jp) {
                uint32_t b4[4];
                ldsm4t(b4, bA + (uint32_t)(ks * 16 * SB * 2 + jp * 32));
#pragma unroll
                for (int im = 0; im < 2; ++im) {
                    // A fragment from transposed ldsm: {r0, r2, r1, r3}
                    mma16816(acc[im][jp * 2 + 0], a4[im][0], a4[im][2],
                             a4[im][1], a4[im][3], b4[0], b4[1]);
                    mma16816(acc[im][jp * 2 + 1], a4[im][0], a4[im][2],
                             a4[im][1], a4[im][3], b4[2], b4[3]);
                }
            }
        }
    }

    // ---- epilogue: regs -> global, + bias (+ residual)
    const int qr = lane >> 2;        // 0..7
    const int qc = (lane & 3) * 2;   // 0,2,4,6
#pragma unroll
    for (int im = 0; im < 2; ++im) {
        int mA = m0 + m0w + im * 16 + qr;
        int mB = mA + 8;
        float bA = bias[mA];
        float bB = bias[mB];
#pragma unroll
        for (int jn = 0; jn < 8; ++jn) {
            int n = l0 + n0w + jn * 8 + qc;
            size_t gA = (size_t)mA * LD + n;
            size_t gB = (size_t)mB * LD + n;
            float o0 = acc[im][jn][0] + bA;
            float o1 = acc[im][jn][1] + bA;
            float o2 = acc[im][jn][2] + bB;
            float o3 = acc[im][jn][3] + bB;
            if (Rn) {
                float2 rA = *(const float2*)(Rn + gA);
                float2 rB = *(const float2*)(Rn + gB);
                o0 += rA.x; o1 += rA.y; o2 += rB.x; o3 += rB.y;
            }
            float2 vA = {o0, o1};
            float2 vB = {o2, o3};
            *(float2*)(Yn + gA) = vA;
            *(float2*)(Yn + gB) = vB;
        }
    }
}

// ---------------------------------------------------------------------------
// context[n,h,kc,vc] = sum_l exp(K[n,h,kc,l]) * V[n,h,vc,l]   (unnormalized)
// Register-tiled 4x4 + register-prefetch pipeline. Staging is row-per-thread:
// thread owns l-row (tid&127) and 16 channels -> STS are 4x STS.128 at banks
// (4l+c), phase-disjoint, zero conflicts. LDGs stay lane-coalesced.
// ---------------------------------------------------------------------------
#define CPAD 36   // floats per l-row (16B aligned, conflict-free fp4 reads)

__global__ __launch_bounds__(256) void context_kernel()
{
    __shared__ float skT[128][CPAD];
    __shared__ float svT[128][CPAD];
    const int n = blockIdx.z, h = blockIdx.y;
    const size_t base = (((size_t)n * NHEADS + h) * HC) * LD;
    const int rowbase = n * CD + h * HC;
    const int tid = threadIdx.x;
    const int grp = tid >> 6;        // 0..3 (l sub-range within 128-tile)
    const int t64 = tid & 63;
    const int kc0 = (t64 >> 3) * 4;  // 0,4,..,28
    const int vc0 = (t64 & 7) * 4;   // 0,4,..,28
    const bool do_ksum = ((t64 & 7) == 0);

    // staging assignment: one l-row, 16 channels per thread
    const int sl  = tid & 127;
    const int sc0 = (tid >> 7) * 16;

    float acc[4][4];
#pragma unroll
    for (int i = 0; i < 4; ++i)
#pragma unroll
        for (int j = 0; j < 4; ++j) acc[i][j] = 0.0f;
    float ks[4] = {0.f, 0.f, 0.f, 0.f};

    float rk[16], rv[16];

#define CTX_LOAD(t)                                                            \
    {                                                                          \
        const int l0c = blockIdx.x * 640 + (t) * 128;                          \
        _Pragma("unroll")                                                      \
        for (int j = 0; j < 16; ++j) {                                         \
            rk[j] = g_K[base + (size_t)(sc0 + j) * LD + l0c + sl];             \
            rv[j] = g_V[base + (size_t)(sc0 + j) * LD + l0c + sl];             \
        }                                                                      \
    }

#define CTX_STORE()                                                            \
    {                                                                          \
        _Pragma("unroll")                                                      \
        for (int j4 = 0; j4 < 4; ++j4) {                                       \
            float4 a;                                                          \
            a.x = __expf(rk[j4 * 4 + 0]);                                      \
            a.y = __expf(rk[j4 * 4 + 1]);                                      \
            a.z = __expf(rk[j4 * 4 + 2]);                                      \
            a.w = __expf(rk[j4 * 4 + 3]);                                      \
            *(float4*)&skT[sl][sc0 + j4 * 4] = a;                              \
            float4 b;                                                          \
            b.x = rv[j4 * 4 + 0];                                              \
            b.y = rv[j4 * 4 + 1];                                              \
            b.z = rv[j4 * 4 + 2];                                              \
            b.w = rv[j4 * 4 + 3];                                              \
            *(float4*)&svT[sl][sc0 + j4 * 4] = b;                              \
        }                                                                      \
    }

    CTX_LOAD(0);

    for (int t = 0; t < 5; ++t) {
        CTX_STORE();
        __syncthreads();
        if (t < 4) CTX_LOAD(t + 1);   // LDGs in flight during compute

#pragma unroll 4
        for (int li = 0; li < 32; ++li) {
            int l = grp * 32 + li;
            float4 a4 = *(const float4*)&skT[l][kc0];
            float4 b4 = *(const float4*)&svT[l][vc0];
            float a[4] = {a4.x, a4.y, a4.z, a4.w};
            float b[4] = {b4.x, b4.y, b4.z, b4.w};
#pragma unroll
            for (int i = 0; i < 4; ++i)
#pragma unroll
                for (int j = 0; j < 4; ++j)
                    acc[i][j] += a[i] * b[j];
            if (do_ksum) {
                ks[0] += a[0]; ks[1] += a[1]; ks[2] += a[2]; ks[3] += a[3];
            }
        }
        __syncthreads();
    }

    if (do_ksum) {
#pragma unroll
        for (int i = 0; i < 4; ++i)
            atomicAdd(&g_ksum[rowbase + kc0 + i], ks[i]);
    }
    float* C = g_CTX + (((size_t)n * NHEADS + h) * HC) * HC;
#pragma unroll
    for (int i = 0; i < 4; ++i)
#pragma unroll
        for (int j = 0; j < 4; ++j)
            atomicAdd(&C[(kc0 + i) * HC + vc0 + j], acc[i][j]);
}

// ---------------------------------------------------------------------------
// attended[n,h,vc,l] = sum_kc (ctx[n,h,kc,vc]/ksum[kc]) * softmax_C(q)[n,h,kc,l]
// Writes bf16 directly for the recovery GEMM.
// ---------------------------------------------------------------------------
__global__ __launch_bounds__(128) void attend_kernel()
{
    __shared__ float4 sctx[32][8];
    const int n = blockIdx.z, h = blockIdx.y;
    const int tid = threadIdx.x;
    const int rowbase = n * CD + h * HC;
    {
        const float4* C = (const float4*)(g_CTX + (((size_t)n * NHEADS + h) * HC) * HC);
#pragma unroll
        for (int s = 0; s < 2; s++) {
            int idx = tid + s * 128;
            float inv = 1.0f / g_ksum[rowbase + (idx >> 3)];
            float4 v = C[idx];
            v.x *= inv; v.y *= inv; v.z *= inv; v.w *= inv;
            sctx[idx >> 3][idx & 7] = v;
        }
    }
    __syncthreads();

    const int l = blockIdx.x * 128 + tid;
    const size_t base = (((size_t)n * NHEADS + h) * HC) * LD + l;

    float q[HC];
    float mx = -1e30f;
#pragma unroll
    for (int c = 0; c < HC; c++) {
        q[c] = g_Q[base + (size_t)c * LD];
        mx = fmaxf(mx, q[c]);
    }
    float s = 0.0f;
#pragma unroll
    for (int c = 0; c < HC; c++) {
        q[c] = __expf(q[c] - mx);
        s += q[c];
    }
    float inv = 1.0f / s;
#pragma unroll
    for (int c = 0; c < HC; c++) q[c] *= inv;

    float acc[HC];
#pragma unroll
    for (int v = 0; v < HC; v++) acc[v] = 0.0f;

#pragma unroll
    for (int kc = 0; kc < HC; kc++) {
        float a = q[kc];
#pragma unroll
        for (int vq = 0; vq < 8; vq++) {
            float4 c4 = sctx[kc][vq];
            acc[vq * 4 + 0] += a * c4.x;
            acc[vq * 4 + 1] += a * c4.y;
            acc[vq * 4 + 2] += a * c4.z;
            acc[vq * 4 + 3] += a * c4.w;
        }
    }
#pragma unroll
    for (int v = 0; v < HC; v++)
        g_ATTbf[base + (size_t)v * LD] = __float2bfloat16(acc[v]);
}

// ---------------------------------------------------------------------------
extern "C" void kernel_launch(void* const* d_in, const int* in_sizes, int n_in,
                              void* d_out, int out_size)
{
    const float* qf = (const float*)d_in[0];
    const float* kf = (const float*)d_in[1];
    const float* vf = (const float*)d_in[2];
    const float* Wq = (const float*)d_in[3];
    const float* bq = (const float*)d_in[4];
    const float* Wk = (const float*)d_in[5];
    const float* bk = (const float*)d_in[6];
    const float* Wv = (const float*)d_in[7];
    const float* bv = (const float*)d_in[8];
    const float* Wr = (const float*)d_in[9];
    const float* br = (const float*)d_in[10];
    float* out = (float*)d_out;

    float *Q, *K, *V;
    __nv_bfloat16 *Qbf, *Kbf, *Vbf, *ATTbf, *Wt;
    cudaGetSymbolAddress((void**)&Q,     g_Q);
    cudaGetSymbolAddress((void**)&K,     g_K);
    cudaGetSymbolAddress((void**)&V,     g_V);
    cudaGetSymbolAddress((void**)&Qbf,   g_Qbf);
    cudaGetSymbolAddress((void**)&Kbf,   g_Kbf);
    cudaGetSymbolAddress((void**)&Vbf,   g_Vbf);
    cudaGetSymbolAddress((void**)&ATTbf, g_ATTbf);
    cudaGetSymbolAddress((void**)&Wt,    g_Wt);
    __nv_bfloat16* Wtq = Wt;
    __nv_bfloat16* Wtk = Wt + 65536;
    __nv_bfloat16* Wtv = Wt + 2 * 65536;
    __nv_bfloat16* Wtr = Wt + 3 * 65536;

    cudaFuncSetAttribute(hmma_gemm_kernel,
                         cudaFuncAttributeMaxDynamicSharedMemorySize, GEMM_SMEM);

    cvt_all_kernel<<<dim3(3200, 4), 256>>>(qf, kf, vf, Wq, Wk, Wv, Wr);    // 1
    zero_kernel<<<264, 256>>>();                                           // 2

    // fused Q/K/V projections: proj = blockIdx.z >> 3
    dim3 fused_grid(LD / 128, CD / 128, 3 * NB);
    hmma_gemm_kernel<<<fused_grid, 256, GEMM_SMEM>>>(                      // 3
        Kbf, Qbf, Vbf, Wtk, Wtq, Wtv, bk, bq, bv, K, Q, V, nullptr);

    context_kernel<<<dim3(10, NHEADS, NB), 256>>>();                       // 4 (ncu)
    attend_kernel<<<dim3(LD / 128, NHEADS, NB), 128>>>();                  // 5

    dim3 gemm_grid(LD / 128, CD / 128, NB);
    hmma_gemm_kernel<<<gemm_grid, 256, GEMM_SMEM>>>(                       // 6
        ATTbf, ATTbf, ATTbf, Wtr, Wtr, Wtr, br, br, br, out, out, out, qf);
}